// round 8
// baseline (speedup 1.0000x reference)
#include <cuda_runtime.h>
#include <cuda_bf16.h>
#include <cstdint>

// ---------------------------------------------------------------------------
// LongShortAttention  (B=4, N=4096, DIM=1024, H=16, DH=64, W=128, S=16, R=1)
// R7: R6's double-buffered tf32 GEMM rewritten WITHOUT device lambdas and
// WITHOUT gridDim.z fusion (both implicated in container kills).  Separate
// Wq/Wkv launches as in the passing R5.  Attention: fixed-max softmax (R5).
// ---------------------------------------------------------------------------

#define NROWS   16384          // B*N
#define SEQ     4096
#define NHEADS  16
#define DH      64
#define BHDIM   64             // B*HEADS
#define WIN     128
#define NWIN    32
#define NSEG    256

// -------------------- scratch (static device globals) ----------------------
__device__ float g_qproj [(size_t)NROWS * 1024];
__device__ float g_kvproj[(size_t)NROWS * 1024];
__device__ float g_q     [(size_t)NROWS * 1024];   // [bh][n][64]
__device__ float g_kv    [(size_t)NROWS * 1024];   // [bh][n][64]
__device__ float g_gkv   [(size_t)BHDIM * NSEG * DH];
__device__ float g_aout  [(size_t)NROWS * 1024];   // [b][t][h*64+d]

// ------------------------------ tf32 helpers -------------------------------
__device__ __forceinline__ uint32_t f2tf32(float v) {
    uint32_t r;
    asm("cvt.rna.tf32.f32 %0, %1;" : "=r"(r) : "f"(v));
    return r;
}

__device__ __forceinline__ void mma_tf32(float* c, const uint32_t* a, const uint32_t* b) {
    asm volatile(
        "mma.sync.aligned.m16n8k8.row.col.f32.tf32.tf32.f32 "
        "{%0,%1,%2,%3}, {%4,%5,%6,%7}, {%8,%9}, {%0,%1,%2,%3};"
        : "+f"(c[0]), "+f"(c[1]), "+f"(c[2]), "+f"(c[3])
        : "r"(a[0]), "r"(a[1]), "r"(a[2]), "r"(a[3]), "r"(b[0]), "r"(b[1]));
}

// ------------------- tf32 tiled GEMM, double-buffered ----------------------
// C(MxN) = A(MxK) @ B(KxN) (+ bias).  128x128 tile, BK=16, 256 thr, 8 warps.
// smem As[s][k][m] / Bs[s][k][n], stride 136 (mod 32 == 8 -> conflict-free
// fragment LDS, validated R2/R5).  One __syncthreads per BK tile.
#define SS 136

// explicit helper (NOT a lambda): global tile -> registers
__device__ __forceinline__ void gemm_gload(const float* Ab, const float* Bb,
                                           int K, int N, int k0,
                                           int aRow, int aCol, int bRow, int bCol,
                                           float4& a0, float4& a1,
                                           float4& b0, float4& b1)
{
    a0 = *(const float4*)(Ab + (size_t)aRow        * K + k0 + aCol);
    a1 = *(const float4*)(Ab + (size_t)(aRow + 64) * K + k0 + aCol);
    b0 = *(const float4*)(Bb + (size_t)(k0 + bRow)     * N + bCol);
    b1 = *(const float4*)(Bb + (size_t)(k0 + bRow + 8) * N + bCol);
}

// explicit helper (NOT a lambda): registers -> smem stage (tf32 rounded)
__device__ __forceinline__ void gemm_sstore(uint32_t (*As)[SS], uint32_t (*Bs)[SS],
                                            int aRow, int aCol, int bRow, int bCol,
                                            const float4& a0, const float4& a1,
                                            const float4& b0, const float4& b1)
{
    As[aCol + 0][aRow]      = f2tf32(a0.x);
    As[aCol + 1][aRow]      = f2tf32(a0.y);
    As[aCol + 2][aRow]      = f2tf32(a0.z);
    As[aCol + 3][aRow]      = f2tf32(a0.w);
    As[aCol + 0][aRow + 64] = f2tf32(a1.x);
    As[aCol + 1][aRow + 64] = f2tf32(a1.y);
    As[aCol + 2][aRow + 64] = f2tf32(a1.z);
    As[aCol + 3][aRow + 64] = f2tf32(a1.w);
    Bs[bRow][bCol + 0]      = f2tf32(b0.x);
    Bs[bRow][bCol + 1]      = f2tf32(b0.y);
    Bs[bRow][bCol + 2]      = f2tf32(b0.z);
    Bs[bRow][bCol + 3]      = f2tf32(b0.w);
    Bs[bRow + 8][bCol + 0]  = f2tf32(b1.x);
    Bs[bRow + 8][bCol + 1]  = f2tf32(b1.y);
    Bs[bRow + 8][bCol + 2]  = f2tf32(b1.z);
    Bs[bRow + 8][bCol + 3]  = f2tf32(b1.w);
}

__global__ __launch_bounds__(256, 2)
void gemm_tf32(const float* __restrict__ A, const float* __restrict__ B,
               const float* __restrict__ bias, float* __restrict__ C,
               int M, int N, int K)
{
    __shared__ uint32_t As[2][16][SS];
    __shared__ uint32_t Bs[2][16][SS];

    const int tid = threadIdx.x;
    const size_t bM = (size_t)blockIdx.y * 128;
    const size_t bN = (size_t)blockIdx.x * 128;

    const float* Ab = A + bM * (size_t)K;
    const float* Bb = B + bN;

    const int aRow = tid >> 2;          // 0..63
    const int aCol = (tid & 3) * 4;     // 0,4,8,12
    const int bRow = tid >> 5;          // 0..7
    const int bCol = (tid & 31) * 4;    // 0..124

    const int wid  = tid >> 5;
    const int lane = tid & 31;
    const int wm   = wid >> 2;
    const int wn   = wid & 3;
    const int mbase = wm * 64;
    const int nbase = wn * 32;
    const int g  = lane >> 2;
    const int tg = lane & 3;

    float acc[4][4][4];
    #pragma unroll
    for (int mt = 0; mt < 4; mt++)
        #pragma unroll
        for (int nt = 0; nt < 4; nt++)
            #pragma unroll
            for (int r = 0; r < 4; r++) acc[mt][nt][r] = 0.f;

    float4 a0, a1, b0, b1;
    const int nKT = K / 16;

    gemm_gload(Ab, Bb, K, N, 0, aRow, aCol, bRow, bCol, a0, a1, b0, b1);
    gemm_sstore(As[0], Bs[0], aRow, aCol, bRow, bCol, a0, a1, b0, b1);
    __syncthreads();

    for (int kt = 0; kt < nKT; kt++) {
        const int buf = kt & 1;

        // issue global loads for the next tile first (latency hidden by mma)
        if (kt + 1 < nKT)
            gemm_gload(Ab, Bb, K, N, (kt + 1) * 16,
                       aRow, aCol, bRow, bCol, a0, a1, b0, b1);

        #pragma unroll
        for (int ks = 0; ks < 2; ks++) {
            const int kk = ks * 8;
            uint32_t afr[4][4], bfr[4][2];
            #pragma unroll
            for (int mt = 0; mt < 4; mt++) {
                const int m0 = mbase + mt * 16 + g;
                afr[mt][0] = As[buf][kk + tg]    [m0];
                afr[mt][1] = As[buf][kk + tg]    [m0 + 8];
                afr[mt][2] = As[buf][kk + tg + 4][m0];
                afr[mt][3] = As[buf][kk + tg + 4][m0 + 8];
            }
            #pragma unroll
            for (int nt = 0; nt < 4; nt++) {
                const int n0 = nbase + nt * 8 + g;
                bfr[nt][0] = Bs[buf][kk + tg]    [n0];
                bfr[nt][1] = Bs[buf][kk + tg + 4][n0];
            }
            #pragma unroll
            for (int mt = 0; mt < 4; mt++)
                #pragma unroll
                for (int nt = 0; nt < 4; nt++)
                    mma_tf32(acc[mt][nt], afr[mt], bfr[nt]);
        }

        // stage the next tile into the other buffer; end-of-iter sync both
        // publishes it and protects buffer reuse in the following iteration
        if (kt + 1 < nKT) {
            gemm_sstore(As[buf ^ 1], Bs[buf ^ 1],
                        aRow, aCol, bRow, bCol, a0, a1, b0, b1);
            __syncthreads();
        }
    }

    #pragma unroll
    for (int mt = 0; mt < 4; mt++) {
        const size_t row0 = bM + mbase + mt * 16 + g;
        #pragma unroll
        for (int nt = 0; nt < 4; nt++) {
            const size_t col = bN + nbase + nt * 8 + tg * 2;
            float bz0 = 0.f, bz1 = 0.f;
            if (bias) { bz0 = bias[col]; bz1 = bias[col + 1]; }
            float2 v0 = make_float2(acc[mt][nt][0] + bz0, acc[mt][nt][1] + bz1);
            float2 v1 = make_float2(acc[mt][nt][2] + bz0, acc[mt][nt][3] + bz1);
            *(float2*)(C + row0 * (size_t)N + col)       = v0;
            *(float2*)(C + (row0 + 8) * (size_t)N + col) = v1;
        }
    }
}

// ------------------------------- rotary ------------------------------------
__global__ __launch_bounds__(256)
void rotary_kernel(const float* __restrict__ qp, const float* __restrict__ kp,
                   float* __restrict__ qo, float* __restrict__ ko)
{
    int idx = blockIdx.x * blockDim.x + threadIdx.x;
    if (idx >= NROWS * 512) return;
    int r = idx >> 9;
    int p = idx & 511;
    int h = p >> 5;
    int i = p & 31;
    int n = r & (SEQ - 1);
    int b = r >> 12;

    float invf  = __powf(10000.f, (-2.f / 64.f) * (float)i);
    float theta = (float)n * invf;
    float s, c;
    sincosf(theta, &s, &c);

    size_t src = (size_t)r * 1024 + h * 64 + i;
    float q0 = qp[src], q1 = qp[src + 32];
    float k0 = kp[src], k1 = kp[src + 32];

    size_t dst = (((size_t)(b * NHEADS + h)) * SEQ + n) * 64 + i;
    const float SC = 0.125f;
    qo[dst]      = (q0 * c - q1 * s) * SC;
    qo[dst + 32] = (q1 * c + q0 * s) * SC;
    ko[dst]      = k0 * c - k1 * s;
    ko[dst + 32] = k1 * c + k0 * s;
}

// ------------------------- global kv aggregation ---------------------------
__global__ __launch_bounds__(32)
void gkv_kernel(const float* __restrict__ kv, const float* __restrict__ Wproj,
                const float* __restrict__ gg, const float* __restrict__ gb,
                float* __restrict__ gkv)
{
    __shared__ float skv[16 * 68];
    __shared__ float swp[64];
    __shared__ float slog[16];

    const int seg  = blockIdx.x;
    const int bh   = blockIdx.y;
    const int lane = threadIdx.x;

    const float* base = kv + ((size_t)bh * SEQ + seg * 16) * 64;
    for (int i = lane; i < 256; i += 32) {
        int s = i >> 4, d4 = (i & 15) << 2;
        *(float4*)&skv[s * 68 + d4] = *(const float4*)(base + s * 64 + d4);
    }
    if (lane < 16) *(float4*)&swp[lane * 4] = *(const float4*)(Wproj + lane * 4);
    __syncwarp();

    if (lane < 16) {
        float a = 0.f;
        #pragma unroll
        for (int d = 0; d < 64; d++) a += skv[lane * 68 + d] * swp[d];
        slog[lane] = a;
    }
    __syncwarp();

    float mx = -1e30f;
    #pragma unroll
    for (int s = 0; s < 16; s++) mx = fmaxf(mx, slog[s]);
    float se = 0.f;
    #pragma unroll
    for (int s = 0; s < 16; s++) se += __expf(slog[s] - mx);
    float inv = 1.f / se;

    float g0 = 0.f, g1 = 0.f;
    #pragma unroll
    for (int s = 0; s < 16; s++) {
        float ps = __expf(slog[s] - mx) * inv;
        g0 += ps * skv[s * 68 + lane];
        g1 += ps * skv[s * 68 + lane + 32];
    }

    float sum = g0 + g1, sq = g0 * g0 + g1 * g1;
    #pragma unroll
    for (int o = 16; o; o >>= 1) {
        sum += __shfl_xor_sync(0xffffffffu, sum, o);
        sq  += __shfl_xor_sync(0xffffffffu, sq, o);
    }
    float mean = sum * (1.f / 64.f);
    float var  = sq * (1.f / 64.f) - mean * mean;
    float rstd = rsqrtf(var + 1e-5f);

    float* outp = gkv + ((size_t)bh * NSEG + seg) * 64;
    outp[lane]      = (g0 - mean) * rstd * gg[lane]      + gb[lane];
    outp[lane + 32] = (g1 - mean) * rstd * gg[lane + 32] + gb[lane + 32];
}

// ------------------------------ attention ----------------------------------
#define KSTRIDE 68
#define FMAX 16.0f

__global__ __launch_bounds__(512, 1)
void attn_kernel(const float* __restrict__ q, const float* __restrict__ kv,
                 const float* __restrict__ gkv, const float* __restrict__ lng_,
                 const float* __restrict__ lnb_, float* __restrict__ out)
{
    extern __shared__ float keys[];     // [512][KSTRIDE]
    __shared__ float s_lng[64], s_lnb[64];

    const int w   = blockIdx.x;
    const int bh  = blockIdx.y;
    const int tid = threadIdx.x;

    if (tid < 64)  { s_lng[tid] = lng_[tid]; s_lnb[tid] = lnb_[tid]; }

    const float* gbase = gkv + (size_t)bh * NSEG * 64;
    for (int idx = tid; idx < 4096; idx += 512) {
        int j = idx >> 4, d4 = (idx & 15) << 2;
        *(float4*)&keys[j * KSTRIDE + d4] = *(const float4*)(gbase + j * 64 + d4);
    }
    const int pos0 = (w - 1) * WIN;
    const float* kbase = kv + (size_t)bh * SEQ * 64;
    for (int idx = tid; idx < 4096; idx += 512) {
        int jj = idx >> 4, d4 = (idx & 15) << 2;
        int pos = pos0 + jj;
        float4 v = make_float4(0.f, 0.f, 0.f, 0.f);
        if (pos >= 0) v = *(const float4*)(kbase + (size_t)pos * 64 + d4);
        *(float4*)&keys[(256 + jj) * KSTRIDE + d4] = v;
    }
    __syncthreads();

    if (tid < 256) {
        int jj = tid;
        if (pos0 + jj >= 0) {
            float* rowp = &keys[(256 + jj) * KSTRIDE];
            float sum = 0.f, sq = 0.f;
            #pragma unroll
            for (int d = 0; d < 64; d++) { float v = rowp[d]; sum += v; sq += v * v; }
            float mean = sum * (1.f / 64.f);
            float var  = sq * (1.f / 64.f) - mean * mean;
            float rstd = rsqrtf(var + 1e-5f);
            #pragma unroll
            for (int d = 0; d < 64; d++)
                rowp[d] = (rowp[d] - mean) * rstd * s_lng[d] + s_lnb[d];
        }
    }
    __syncthreads();

    const int row  = tid >> 2;
    const int quad = tid & 3;
    const int t    = w * WIN + row;
    const int d0   = quad * 16;

    float qr[16], acc[16];
    const float* qp = q + ((size_t)bh * SEQ + t) * 64 + d0;
    #pragma unroll
    for (int m = 0; m < 4; m++) *(float4*)&qr[m * 4] = *(const float4*)(qp + m * 4);
    #pragma unroll
    for (int d = 0; d < 16; d++) acc[d] = 0.f;

    float l = 0.f;

    const int nglobal = t >> 4;
    const int locmax  = 128 + row;
    const int locmin  = (w == 0) ? 128 : 0;

    const int warpid   = tid >> 5;
    const int rowMaxW  = warpid * 8 + 7;
    const int gLimW    = min(NSEG, (w * WIN + rowMaxW) >> 4);
    const int locMaxW  = 128 + rowMaxW;

    #pragma unroll 2
    for (int j = 0; j < gLimW; j++) {
        const float* kp2 = &keys[j * KSTRIDE + d0];
        float kr[16];
        *(float4*)&kr[0]  = *(const float4*)(kp2);
        *(float4*)&kr[4]  = *(const float4*)(kp2 + 4);
        *(float4*)&kr[8]  = *(const float4*)(kp2 + 8);
        *(float4*)&kr[12] = *(const float4*)(kp2 + 12);
        float dp = 0.f;
        #pragma unroll
        for (int d = 0; d < 16; d++) dp += kr[d] * qr[d];
        dp += __shfl_xor_sync(0xffffffffu, dp, 1);
        dp += __shfl_xor_sync(0xffffffffu, dp, 2);
        if (j < nglobal) {
            float p2 = __expf(dp - FMAX);
            l += p2;
            #pragma unroll
            for (int d = 0; d < 16; d++) acc[d] += p2 * kr[d];
        }
    }
    #pragma unroll 2
    for (int jj = locmin; jj <= locMaxW; jj++) {
        const float* kp2 = &keys[(256 + jj) * KSTRIDE + d0];
        float kr[16];
        *(float4*)&kr[0]  = *(const float4*)(kp2);
        *(float4*)&kr[4]  = *(const float4*)(kp2 + 4);
        *(float4*)&kr[8]  = *(const float4*)(kp2 + 8);
        *(float4*)&kr[12] = *(const float4*)(kp2 + 12);
        float dp = 0.f;
        #pragma unroll
        for (int d = 0; d < 16; d++) dp += kr[d] * qr[d];
        dp += __shfl_xor_sync(0xffffffffu, dp, 1);
        dp += __shfl_xor_sync(0xffffffffu, dp, 2);
        if (jj <= locmax) {
            float p2 = __expf(dp - FMAX);
            l += p2;
            #pragma unroll
            for (int d = 0; d < 16; d++) acc[d] += p2 * kr[d];
        }
    }

    float inv = 1.f / l;
    const int b = bh >> 4, h = bh & 15;
    float* op = out + ((size_t)b * SEQ + t) * 1024 + h * 64 + d0;
    #pragma unroll
    for (int m = 0; m < 4; m++) {
        float4 v;
        v.x = acc[m * 4 + 0] * inv;
        v.y = acc[m * 4 + 1] * inv;
        v.z = acc[m * 4 + 2] * inv;
        v.w = acc[m * 4 + 3] * inv;
        *(float4*)(op + m * 4) = v;
    }
}

// ------------------------------ launcher -----------------------------------
extern "C" void kernel_launch(void* const* d_in, const int* in_sizes, int n_in,
                              void* d_out, int out_size)
{
    const float* x     = (const float*)d_in[0];
    const float* Wq    = (const float*)d_in[1];
    const float* Wkv   = (const float*)d_in[2];
    const float* Wproj = (const float*)d_in[3];
    const float* Wout  = (const float*)d_in[4];
    const float* bout  = (const float*)d_in[5];
    const float* lng   = (const float*)d_in[6];
    const float* lnb   = (const float*)d_in[7];
    const float* gng   = (const float*)d_in[8];
    const float* gnb   = (const float*)d_in[9];
    float* out = (float*)d_out;

    float *qproj, *kvproj, *qb, *kvb, *gkvb, *aout;
    cudaGetSymbolAddress((void**)&qproj,  g_qproj);
    cudaGetSymbolAddress((void**)&kvproj, g_kvproj);
    cudaGetSymbolAddress((void**)&qb,     g_q);
    cudaGetSymbolAddress((void**)&kvb,    g_kv);
    cudaGetSymbolAddress((void**)&gkvb,   g_gkv);
    cudaGetSymbolAddress((void**)&aout,   g_aout);

    dim3 gg1(1024 / 128, NROWS / 128);     // (8, 128)
    gemm_tf32<<<gg1, 256>>>(x, Wq,  nullptr, qproj,  NROWS, 1024, 1024);
    gemm_tf32<<<gg1, 256>>>(x, Wkv, nullptr, kvproj, NROWS, 1024, 1024);

    rotary_kernel<<<(NROWS * 512) / 256, 256>>>(qproj, kvproj, qb, kvb);

    gkv_kernel<<<dim3(NSEG, BHDIM), 32>>>(kvb, Wproj, gng, gnb, gkvb);

    int smem = 512 * KSTRIDE * sizeof(float);   // 139264 B
    cudaFuncSetAttribute(attn_kernel, cudaFuncAttributeMaxDynamicSharedMemorySize, smem);
    attn_kernel<<<dim3(NWIN, BHDIM), 512, smem>>>(qb, kvb, gkvb, lng, lnb, aout);

    gemm_tf32<<<gg1, 256>>>(aout, Wout, bout, out, NROWS, 1024, 1024);
}

// round 10
// speedup vs baseline: 1.1542x; 1.1542x over previous
#include <cuda_runtime.h>
#include <cuda_fp16.h>
#include <cstdint>

// ---------------------------------------------------------------------------
// LongShortAttention  (B=4, N=4096, DIM=1024, H=16, DH=64, W=128, S=16, R=1)
// R9: harness target is sm_100 (NO 'a') -> tcgen05 unavailable.  Legacy mma
// is issue-bound, so GEMMs switch to m16n8k16.f16 (2x MACs/instruction,
// fp16 mantissa == tf32 mantissa).  Attention etc unchanged from R5.
// ---------------------------------------------------------------------------

#define NROWS   16384          // B*N
#define SEQ     4096
#define NHEADS  16
#define DH      64
#define BHDIM   64             // B*HEADS
#define WIN     128
#define NWIN    32
#define NSEG    256

// -------------------- scratch (static device globals) ----------------------
__device__ float g_qproj [(size_t)NROWS * 1024];
__device__ float g_kvproj[(size_t)NROWS * 1024];
__device__ float g_q     [(size_t)NROWS * 1024];   // [bh][n][64]
__device__ float g_kv    [(size_t)NROWS * 1024];   // [bh][n][64]
__device__ float g_gkv   [(size_t)BHDIM * NSEG * DH];
__device__ float g_aout  [(size_t)NROWS * 1024];   // [b][t][h*64+d]

// ------------------------------ helpers ------------------------------------
__device__ __forceinline__ uint32_t h2pack(float lo, float hi) {
    __half2 h = __floats2half2_rn(lo, hi);
    return *(uint32_t*)&h;
}

__device__ __forceinline__ void mma_f16(float* c, const uint32_t* a, const uint32_t* b) {
    asm volatile(
        "mma.sync.aligned.m16n8k16.row.col.f32.f16.f16.f32 "
        "{%0,%1,%2,%3}, {%4,%5,%6,%7}, {%8,%9}, {%0,%1,%2,%3};"
        : "+f"(c[0]), "+f"(c[1]), "+f"(c[2]), "+f"(c[3])
        : "r"(a[0]), "r"(a[1]), "r"(a[2]), "r"(a[3]), "r"(b[0]), "r"(b[1]));
}

// --------------------------- f16 tiled GEMM --------------------------------
// C(MxN) = A(MxK) @ B(KxN) (+ bias).  128x128 block tile, BK=16, 256 thr,
// 8 warps as 2x4, warp tile 64x32 = 4x4 m16n8k16 mma tiles (ONE k-step).
// smem half2: As2[k2][m] = {A[m][2k2],A[m][2k2+1]},  Bs2[k2][n] =
// {B[2k2][n],B[2k2+1][n]},  row stride 136 (4B units; mod 32 == 8) ->
// fragment LDS banks (tg*8 + g) all-distinct, conflict-free (R2-validated).
#define SS 136

__global__ __launch_bounds__(256, 2)
void gemm_f16t(const float* __restrict__ A, const float* __restrict__ B,
               const float* __restrict__ bias, float* __restrict__ C,
               int M, int N, int K)
{
    __shared__ uint32_t As2[8][SS];
    __shared__ uint32_t Bs2[8][SS];

    const int tid = threadIdx.x;
    const size_t bM = (size_t)blockIdx.y * 128;
    const size_t bN = (size_t)blockIdx.x * 128;

    const float* Ab = A + bM * (size_t)K;
    const float* Bb = B + bN;

    // A fill: thread -> rows aRow, aRow+64; k cols aCol..aCol+3
    const int aRow  = tid >> 2;          // 0..63
    const int aCol  = (tid & 3) * 4;     // 0,4,8,12
    const int aCol2 = aCol >> 1;         // 0,2,4,6  (half2 k-index)
    // B fill: thread -> k-pair row bRow2 (covers k = 2*bRow2, 2*bRow2+1),
    // n cols bCol..bCol+3
    const int bRow2 = tid >> 5;          // 0..7
    const int bCol  = (tid & 31) * 4;    // 0..124

    const int wid  = tid >> 5;
    const int lane = tid & 31;
    const int wm   = wid >> 2;
    const int wn   = wid & 3;
    const int mbase = wm * 64;
    const int nbase = wn * 32;
    const int g  = lane >> 2;
    const int tg = lane & 3;

    float acc[4][4][4];
    #pragma unroll
    for (int mt = 0; mt < 4; mt++)
        #pragma unroll
        for (int nt = 0; nt < 4; nt++)
            #pragma unroll
            for (int r = 0; r < 4; r++) acc[mt][nt][r] = 0.f;

    float4 a0 = *(const float4*)(Ab + (size_t)aRow        * K + aCol);
    float4 a1 = *(const float4*)(Ab + (size_t)(aRow + 64) * K + aCol);
    float4 b0 = *(const float4*)(Bb + (size_t)(2 * bRow2)     * N + bCol);
    float4 b1 = *(const float4*)(Bb + (size_t)(2 * bRow2 + 1) * N + bCol);

    for (int k0 = 0; k0 < K; k0 += 16) {
        // ---- stores (fp16 conversion happens here) ----
        As2[aCol2 + 0][aRow]      = h2pack(a0.x, a0.y);
        As2[aCol2 + 1][aRow]      = h2pack(a0.z, a0.w);
        As2[aCol2 + 0][aRow + 64] = h2pack(a1.x, a1.y);
        As2[aCol2 + 1][aRow + 64] = h2pack(a1.z, a1.w);
        // B: pack across the two k rows -> {B[2k2][n], B[2k2+1][n]}
        Bs2[bRow2][bCol + 0] = h2pack(b0.x, b1.x);
        Bs2[bRow2][bCol + 1] = h2pack(b0.y, b1.y);
        Bs2[bRow2][bCol + 2] = h2pack(b0.z, b1.z);
        Bs2[bRow2][bCol + 3] = h2pack(b0.w, b1.w);
        __syncthreads();

        if (k0 + 16 < K) {
            a0 = *(const float4*)(Ab + (size_t)aRow        * K + k0 + 16 + aCol);
            a1 = *(const float4*)(Ab + (size_t)(aRow + 64) * K + k0 + 16 + aCol);
            b0 = *(const float4*)(Bb + (size_t)(k0 + 16 + 2 * bRow2)     * N + bCol);
            b1 = *(const float4*)(Bb + (size_t)(k0 + 16 + 2 * bRow2 + 1) * N + bCol);
        }

        // ---- one m16n8k16 step covers the whole BK=16 ----
        {
            uint32_t afr[4][4], bfr[4][2];
            #pragma unroll
            for (int mt = 0; mt < 4; mt++) {
                const int m0 = mbase + mt * 16 + g;
                afr[mt][0] = As2[tg]    [m0];        // k = 2tg, 2tg+1
                afr[mt][1] = As2[tg]    [m0 + 8];
                afr[mt][2] = As2[tg + 4][m0];        // k = 2tg+8, 2tg+9
                afr[mt][3] = As2[tg + 4][m0 + 8];
            }
            #pragma unroll
            for (int nt = 0; nt < 4; nt++) {
                const int n0 = nbase + nt * 8 + g;
                bfr[nt][0] = Bs2[tg]    [n0];
                bfr[nt][1] = Bs2[tg + 4][n0];
            }
            #pragma unroll
            for (int mt = 0; mt < 4; mt++)
                #pragma unroll
                for (int nt = 0; nt < 4; nt++)
                    mma_f16(acc[mt][nt], afr[mt], bfr[nt]);
        }
        __syncthreads();
    }

    #pragma unroll
    for (int mt = 0; mt < 4; mt++) {
        const size_t row0 = bM + mbase + mt * 16 + g;
        #pragma unroll
        for (int nt = 0; nt < 4; nt++) {
            const size_t col = bN + nbase + nt * 8 + tg * 2;
            float bz0 = 0.f, bz1 = 0.f;
            if (bias) { bz0 = bias[col]; bz1 = bias[col + 1]; }
            float2 v0 = make_float2(acc[mt][nt][0] + bz0, acc[mt][nt][1] + bz1);
            float2 v1 = make_float2(acc[mt][nt][2] + bz0, acc[mt][nt][3] + bz1);
            *(float2*)(C + row0 * (size_t)N + col)       = v0;
            *(float2*)(C + (row0 + 8) * (size_t)N + col) = v1;
        }
    }
}

// ------------------------------- rotary ------------------------------------
__global__ __launch_bounds__(256)
void rotary_kernel(const float* __restrict__ qp, const float* __restrict__ kp,
                   float* __restrict__ qo, float* __restrict__ ko)
{
    int idx = blockIdx.x * blockDim.x + threadIdx.x;
    if (idx >= NROWS * 512) return;
    int r = idx >> 9;
    int p = idx & 511;
    int h = p >> 5;
    int i = p & 31;
    int n = r & (SEQ - 1);
    int b = r >> 12;

    float invf  = __powf(10000.f, (-2.f / 64.f) * (float)i);
    float theta = (float)n * invf;
    float s, c;
    sincosf(theta, &s, &c);

    size_t src = (size_t)r * 1024 + h * 64 + i;
    float q0 = qp[src], q1 = qp[src + 32];
    float k0 = kp[src], k1 = kp[src + 32];

    size_t dst = (((size_t)(b * NHEADS + h)) * SEQ + n) * 64 + i;
    const float SC = 0.125f;
    qo[dst]      = (q0 * c - q1 * s) * SC;
    qo[dst + 32] = (q1 * c + q0 * s) * SC;
    ko[dst]      = k0 * c - k1 * s;
    ko[dst + 32] = k1 * c + k0 * s;
}

// ------------------------- global kv aggregation ---------------------------
__global__ __launch_bounds__(32)
void gkv_kernel(const float* __restrict__ kv, const float* __restrict__ Wproj,
                const float* __restrict__ gg, const float* __restrict__ gb,
                float* __restrict__ gkv)
{
    __shared__ float skv[16 * 68];
    __shared__ float swp[64];
    __shared__ float slog[16];

    const int seg  = blockIdx.x;
    const int bh   = blockIdx.y;
    const int lane = threadIdx.x;

    const float* base = kv + ((size_t)bh * SEQ + seg * 16) * 64;
    for (int i = lane; i < 256; i += 32) {
        int s = i >> 4, d4 = (i & 15) << 2;
        *(float4*)&skv[s * 68 + d4] = *(const float4*)(base + s * 64 + d4);
    }
    if (lane < 16) *(float4*)&swp[lane * 4] = *(const float4*)(Wproj + lane * 4);
    __syncwarp();

    if (lane < 16) {
        float a = 0.f;
        #pragma unroll
        for (int d = 0; d < 64; d++) a += skv[lane * 68 + d] * swp[d];
        slog[lane] = a;
    }
    __syncwarp();

    float mx = -1e30f;
    #pragma unroll
    for (int s = 0; s < 16; s++) mx = fmaxf(mx, slog[s]);
    float se = 0.f;
    #pragma unroll
    for (int s = 0; s < 16; s++) se += __expf(slog[s] - mx);
    float inv = 1.f / se;

    float g0 = 0.f, g1 = 0.f;
    #pragma unroll
    for (int s = 0; s < 16; s++) {
        float ps = __expf(slog[s] - mx) * inv;
        g0 += ps * skv[s * 68 + lane];
        g1 += ps * skv[s * 68 + lane + 32];
    }

    float sum = g0 + g1, sq = g0 * g0 + g1 * g1;
    #pragma unroll
    for (int o = 16; o; o >>= 1) {
        sum += __shfl_xor_sync(0xffffffffu, sum, o);
        sq  += __shfl_xor_sync(0xffffffffu, sq, o);
    }
    float mean = sum * (1.f / 64.f);
    float var  = sq * (1.f / 64.f) - mean * mean;
    float rstd = rsqrtf(var + 1e-5f);

    float* outp = gkv + ((size_t)bh * NSEG + seg) * 64;
    outp[lane]      = (g0 - mean) * rstd * gg[lane]      + gb[lane];
    outp[lane + 32] = (g1 - mean) * rstd * gg[lane + 32] + gb[lane + 32];
}

// ------------------------------ attention ----------------------------------
#define KSTRIDE 68
#define FMAX 16.0f

__global__ __launch_bounds__(512, 1)
void attn_kernel(const float* __restrict__ q, const float* __restrict__ kv,
                 const float* __restrict__ gkv, const float* __restrict__ lng_,
                 const float* __restrict__ lnb_, float* __restrict__ out)
{
    extern __shared__ float keys[];     // [512][KSTRIDE]
    __shared__ float s_lng[64], s_lnb[64];

    const int w   = blockIdx.x;
    const int bh  = blockIdx.y;
    const int tid = threadIdx.x;

    if (tid < 64)  { s_lng[tid] = lng_[tid]; s_lnb[tid] = lnb_[tid]; }

    const float* gbase = gkv + (size_t)bh * NSEG * 64;
    for (int idx = tid; idx < 4096; idx += 512) {
        int j = idx >> 4, d4 = (idx & 15) << 2;
        *(float4*)&keys[j * KSTRIDE + d4] = *(const float4*)(gbase + j * 64 + d4);
    }
    const int pos0 = (w - 1) * WIN;
    const float* kbase = kv + (size_t)bh * SEQ * 64;
    for (int idx = tid; idx < 4096; idx += 512) {
        int jj = idx >> 4, d4 = (idx & 15) << 2;
        int pos = pos0 + jj;
        float4 v = make_float4(0.f, 0.f, 0.f, 0.f);
        if (pos >= 0) v = *(const float4*)(kbase + (size_t)pos * 64 + d4);
        *(float4*)&keys[(256 + jj) * KSTRIDE + d4] = v;
    }
    __syncthreads();

    if (tid < 256) {
        int jj = tid;
        if (pos0 + jj >= 0) {
            float* rowp = &keys[(256 + jj) * KSTRIDE];
            float sum = 0.f, sq = 0.f;
            #pragma unroll
            for (int d = 0; d < 64; d++) { float v = rowp[d]; sum += v; sq += v * v; }
            float mean = sum * (1.f / 64.f);
            float var  = sq * (1.f / 64.f) - mean * mean;
            float rstd = rsqrtf(var + 1e-5f);
            #pragma unroll
            for (int d = 0; d < 64; d++)
                rowp[d] = (rowp[d] - mean) * rstd * s_lng[d] + s_lnb[d];
        }
    }
    __syncthreads();

    const int row  = tid >> 2;
    const int quad = tid & 3;
    const int t    = w * WIN + row;
    const int d0   = quad * 16;

    float qr[16], acc[16];
    const float* qp = q + ((size_t)bh * SEQ + t) * 64 + d0;
    #pragma unroll
    for (int m = 0; m < 4; m++) *(float4*)&qr[m * 4] = *(const float4*)(qp + m * 4);
    #pragma unroll
    for (int d = 0; d < 16; d++) acc[d] = 0.f;

    float l = 0.f;

    const int nglobal = t >> 4;
    const int locmax  = 128 + row;
    const int locmin  = (w == 0) ? 128 : 0;

    const int warpid   = tid >> 5;
    const int rowMaxW  = warpid * 8 + 7;
    const int gLimW    = min(NSEG, (w * WIN + rowMaxW) >> 4);
    const int locMaxW  = 128 + rowMaxW;

    #pragma unroll 2
    for (int j = 0; j < gLimW; j++) {
        const float* kp2 = &keys[j * KSTRIDE + d0];
        float kr[16];
        *(float4*)&kr[0]  = *(const float4*)(kp2);
        *(float4*)&kr[4]  = *(const float4*)(kp2 + 4);
        *(float4*)&kr[8]  = *(const float4*)(kp2 + 8);
        *(float4*)&kr[12] = *(const float4*)(kp2 + 12);
        float dp = 0.f;
        #pragma unroll
        for (int d = 0; d < 16; d++) dp += kr[d] * qr[d];
        dp += __shfl_xor_sync(0xffffffffu, dp, 1);
        dp += __shfl_xor_sync(0xffffffffu, dp, 2);
        if (j < nglobal) {
            float p2 = __expf(dp - FMAX);
            l += p2;
            #pragma unroll
            for (int d = 0; d < 16; d++) acc[d] += p2 * kr[d];
        }
    }
    #pragma unroll 2
    for (int jj = locmin; jj <= locMaxW; jj++) {
        const float* kp2 = &keys[(256 + jj) * KSTRIDE + d0];
        float kr[16];
        *(float4*)&kr[0]  = *(const float4*)(kp2);
        *(float4*)&kr[4]  = *(const float4*)(kp2 + 4);
        *(float4*)&kr[8]  = *(const float4*)(kp2 + 8);
        *(float4*)&kr[12] = *(const float4*)(kp2 + 12);
        float dp = 0.f;
        #pragma unroll
        for (int d = 0; d < 16; d++) dp += kr[d] * qr[d];
        dp += __shfl_xor_sync(0xffffffffu, dp, 1);
        dp += __shfl_xor_sync(0xffffffffu, dp, 2);
        if (jj <= locmax) {
            float p2 = __expf(dp - FMAX);
            l += p2;
            #pragma unroll
            for (int d = 0; d < 16; d++) acc[d] += p2 * kr[d];
        }
    }

    float inv = 1.f / l;
    const int b = bh >> 4, h = bh & 15;
    float* op = out + ((size_t)b * SEQ + t) * 1024 + h * 64 + d0;
    #pragma unroll
    for (int m = 0; m < 4; m++) {
        float4 v;
        v.x = acc[m * 4 + 0] * inv;
        v.y = acc[m * 4 + 1] * inv;
        v.z = acc[m * 4 + 2] * inv;
        v.w = acc[m * 4 + 3] * inv;
        *(float4*)(op + m * 4) = v;
    }
}

// ------------------------------ launcher -----------------------------------
extern "C" void kernel_launch(void* const* d_in, const int* in_sizes, int n_in,
                              void* d_out, int out_size)
{
    const float* x     = (const float*)d_in[0];
    const float* Wq    = (const float*)d_in[1];
    const float* Wkv   = (const float*)d_in[2];
    const float* Wproj = (const float*)d_in[3];
    const float* Wout  = (const float*)d_in[4];
    const float* bout  = (const float*)d_in[5];
    const float* lng   = (const float*)d_in[6];
    const float* lnb   = (const float*)d_in[7];
    const float* gng   = (const float*)d_in[8];
    const float* gnb   = (const float*)d_in[9];
    float* out = (float*)d_out;

    float *qproj, *kvproj, *qb, *kvb, *gkvb, *aout;
    cudaGetSymbolAddress((void**)&qproj,  g_qproj);
    cudaGetSymbolAddress((void**)&kvproj, g_kvproj);
    cudaGetSymbolAddress((void**)&qb,     g_q);
    cudaGetSymbolAddress((void**)&kvb,    g_kv);
    cudaGetSymbolAddress((void**)&gkvb,   g_gkv);
    cudaGetSymbolAddress((void**)&aout,   g_aout);

    dim3 gg1(1024 / 128, NROWS / 128);     // (8, 128)
    gemm_f16t<<<gg1, 256>>>(x, Wq,  nullptr, qproj,  NROWS, 1024, 1024);
    gemm_f16t<<<gg1, 256>>>(x, Wkv, nullptr, kvproj, NROWS, 1024, 1024);

    rotary_kernel<<<(NROWS * 512) / 256, 256>>>(qproj, kvproj, qb, kvb);

    gkv_kernel<<<dim3(NSEG, BHDIM), 32>>>(kvb, Wproj, gng, gnb, gkvb);

    int smem = 512 * KSTRIDE * sizeof(float);   // 139264 B
    cudaFuncSetAttribute(attn_kernel, cudaFuncAttributeMaxDynamicSharedMemorySize, smem);
    attn_kernel<<<dim3(NWIN, BHDIM), 512, smem>>>(qb, kvb, gkvb, lng, lnb, aout);

    gemm_f16t<<<gg1, 256>>>(aout, Wout, bout, out, NROWS, 1024, 1024);
}

// round 11
// speedup vs baseline: 1.2603x; 1.0919x over previous
#include <cuda_runtime.h>
#include <cuda_fp16.h>
#include <cstdint>

// ---------------------------------------------------------------------------
// LongShortAttention  (B=4, N=4096, DIM=1024, H=16, DH=64, W=128, S=16, R=1)
// R10: GEMM operands pre-converted to fp16 in gmem (bit-identical mma inputs);
// fragment loads via ldmatrix (A non-trans, B trans); BK=32.  Attention
// writes half output directly.  Attention math unchanged (R5 fixed-max).
// ---------------------------------------------------------------------------

#define NROWS   16384          // B*N
#define SEQ     4096
#define NHEADS  16
#define DH      64
#define BHDIM   64             // B*HEADS
#define WIN     128
#define NWIN    32
#define NSEG    256

// -------------------- scratch (static device globals) ----------------------
__device__ float  g_qproj [(size_t)NROWS * 1024];
__device__ float  g_kvproj[(size_t)NROWS * 1024];
__device__ float  g_q     [(size_t)NROWS * 1024];   // [bh][n][64]
__device__ float  g_kv    [(size_t)NROWS * 1024];   // [bh][n][64]
__device__ float  g_gkv   [(size_t)BHDIM * NSEG * DH];
__device__ __half g_xh    [(size_t)NROWS * 1024];
__device__ __half g_wqh   [1024 * 1024];
__device__ __half g_wkvh  [1024 * 1024];
__device__ __half g_wouth [1024 * 1024];
__device__ __half g_aouth [(size_t)NROWS * 1024];   // [b][t][h*64+d]

// ------------------------------ helpers ------------------------------------
__device__ __forceinline__ void mma_f16(float* c, const uint32_t* a, const uint32_t* b) {
    asm volatile(
        "mma.sync.aligned.m16n8k16.row.col.f32.f16.f16.f32 "
        "{%0,%1,%2,%3}, {%4,%5,%6,%7}, {%8,%9}, {%0,%1,%2,%3};"
        : "+f"(c[0]), "+f"(c[1]), "+f"(c[2]), "+f"(c[3])
        : "r"(a[0]), "r"(a[1]), "r"(a[2]), "r"(a[3]), "r"(b[0]), "r"(b[1]));
}

__device__ __forceinline__ void ldm_x4(uint32_t* r, uint32_t addr) {
    asm volatile("ldmatrix.sync.aligned.m8n8.x4.shared.b16 {%0,%1,%2,%3}, [%4];"
        : "=r"(r[0]), "=r"(r[1]), "=r"(r[2]), "=r"(r[3]) : "r"(addr));
}

__device__ __forceinline__ void ldm_x4_t(uint32_t* r, uint32_t addr) {
    asm volatile("ldmatrix.sync.aligned.m8n8.x4.trans.shared.b16 {%0,%1,%2,%3}, [%4];"
        : "=r"(r[0]), "=r"(r[1]), "=r"(r[2]), "=r"(r[3]) : "r"(addr));
}

// ------------------------ fp32 -> fp16 conversion --------------------------
__global__ __launch_bounds__(256)
void cvt_f2h(const float* __restrict__ src, __half* __restrict__ dst, int n)
{
    int i = (blockIdx.x * blockDim.x + threadIdx.x) * 8;
    if (i >= n) return;
    float4 v0 = *(const float4*)(src + i);
    float4 v1 = *(const float4*)(src + i + 4);
    __half2 h0 = __floats2half2_rn(v0.x, v0.y);
    __half2 h1 = __floats2half2_rn(v0.z, v0.w);
    __half2 h2 = __floats2half2_rn(v1.x, v1.y);
    __half2 h3 = __floats2half2_rn(v1.z, v1.w);
    uint4 u;
    u.x = *(uint32_t*)&h0; u.y = *(uint32_t*)&h1;
    u.z = *(uint32_t*)&h2; u.w = *(uint32_t*)&h3;
    *(uint4*)(dst + i) = u;
}

// --------------------------- f16 tiled GEMM --------------------------------
// C(MxN) = A(MxK) @ B(KxN) (+ bias), A/B fp16 in gmem.  128x128 tile, BK=32,
// 256 thr, 8 warps as 2x4, warp tile 64x32, m16n8k16.
// smem: As[m][k] rows 64B+16 pad = 80B (store bank walk r*20%32 distinct;
//       ldmatrix 8-row phases cover all 32 banks);
//       Bs[k][n] rows 256B+16 pad = 272B (r*68%32 -> r*4%32 distinct).
#define A_STR 80
#define B_STR 272

__global__ __launch_bounds__(256, 2)
void gemm_f16ldm(const __half* __restrict__ A, const __half* __restrict__ B,
                 const float* __restrict__ bias, float* __restrict__ C,
                 int M, int N, int K)
{
    __shared__ __align__(16) char sA[128 * A_STR];   // 10240 B
    __shared__ __align__(16) char sB[32 * B_STR];    // 8704 B

    const int tid = threadIdx.x;
    const size_t bM = (size_t)blockIdx.y * 128;
    const size_t bN = (size_t)blockIdx.x * 128;

    const __half* Ab = A + bM * (size_t)K;
    const __half* Bb = B + bN;

    // fill indices: A chunk c=tid,tid+256 -> row c>>2 (0..127), off16 c&3
    const int aRow = tid >> 2;          // 0..63 (+64 for second chunk)
    const int aOff = tid & 3;           // 16B chunk within 64B row
    // B chunk -> row c>>4 (0..31), off16 c&15
    const int bRow = tid >> 4;          // 0..15 (+16)
    const int bOff = tid & 15;

    const int wid  = tid >> 5;
    const int lane = tid & 31;
    const int wm   = wid >> 2;
    const int wn   = wid & 3;
    const int mbase = wm * 64;
    const int nbase = wn * 32;
    const int g  = lane >> 2;
    const int tg = lane & 3;
    const int part = lane >> 3;         // 0..3 (ldmatrix sub-matrix)
    const int r8   = lane & 7;

    const uint32_t sA32 = (uint32_t)__cvta_generic_to_shared(sA);
    const uint32_t sB32 = (uint32_t)__cvta_generic_to_shared(sB);

    float acc[4][4][4];
    #pragma unroll
    for (int mt = 0; mt < 4; mt++)
        #pragma unroll
        for (int nt = 0; nt < 4; nt++)
            #pragma unroll
            for (int r = 0; r < 4; r++) acc[mt][nt][r] = 0.f;

    uint4 pa0 = *(const uint4*)(Ab + (size_t)aRow        * K + aOff * 8);
    uint4 pa1 = *(const uint4*)(Ab + (size_t)(aRow + 64) * K + aOff * 8);
    uint4 pb0 = *(const uint4*)(Bb + (size_t)bRow        * N + bOff * 8);
    uint4 pb1 = *(const uint4*)(Bb + (size_t)(bRow + 16) * N + bOff * 8);

    const int nKT = K / 32;
    for (int kt = 0; kt < nKT; kt++) {
        *(uint4*)(sA + aRow        * A_STR + aOff * 16) = pa0;
        *(uint4*)(sA + (aRow + 64) * A_STR + aOff * 16) = pa1;
        *(uint4*)(sB + bRow        * B_STR + bOff * 16) = pb0;
        *(uint4*)(sB + (bRow + 16) * B_STR + bOff * 16) = pb1;
        __syncthreads();

        if (kt + 1 < nKT) {
            const int k0 = (kt + 1) * 32;
            pa0 = *(const uint4*)(Ab + (size_t)aRow        * K + k0 + aOff * 8);
            pa1 = *(const uint4*)(Ab + (size_t)(aRow + 64) * K + k0 + aOff * 8);
            pb0 = *(const uint4*)(Bb + (size_t)(k0 + bRow)      * N + bOff * 8);
            pb1 = *(const uint4*)(Bb + (size_t)(k0 + bRow + 16) * N + bOff * 8);
        }

        #pragma unroll
        for (int ks = 0; ks < 2; ks++) {
            uint32_t afr[4][4], bfr[4][2];
            // A fragments: non-trans x4; sub-matrices (m+0-7,k0-7),(m+8-15,k0-7),
            // (m+0-7,k8-15),(m+8-15,k8-15) -> exactly {a0,a1,a2,a3}
            #pragma unroll
            for (int mt = 0; mt < 4; mt++) {
                const int row = mbase + mt * 16 + r8 + (part & 1) * 8;
                const uint32_t byte = (uint32_t)(ks * 32 + (part >> 1) * 16);
                ldm_x4(afr[mt], sA32 + row * A_STR + byte);
            }
            // B fragments: trans x4 over Bs[k][n]; sub-matrices (k0-7,n0-7),
            // (k8-15,n0-7),(k0-7,n8-15),(k8-15,n8-15) -> {b0,b1} of two n8 tiles
            #pragma unroll
            for (int np = 0; np < 2; np++) {
                uint32_t t[4];
                const int row = ks * 16 + r8 + (part & 1) * 8;
                const uint32_t byte = (uint32_t)((nbase + np * 16) * 2 + (part >> 1) * 16);
                ldm_x4_t(t, sB32 + row * B_STR + byte);
                bfr[2 * np][0]     = t[0];
                bfr[2 * np][1]     = t[1];
                bfr[2 * np + 1][0] = t[2];
                bfr[2 * np + 1][1] = t[3];
            }
            #pragma unroll
            for (int mt = 0; mt < 4; mt++)
                #pragma unroll
                for (int nt = 0; nt < 4; nt++)
                    mma_f16(acc[mt][nt], afr[mt], bfr[nt]);
        }
        __syncthreads();
    }

    #pragma unroll
    for (int mt = 0; mt < 4; mt++) {
        const size_t row0 = bM + mbase + mt * 16 + g;
        #pragma unroll
        for (int nt = 0; nt < 4; nt++) {
            const size_t col = bN + nbase + nt * 8 + tg * 2;
            float bz0 = 0.f, bz1 = 0.f;
            if (bias) { bz0 = bias[col]; bz1 = bias[col + 1]; }
            float2 v0 = make_float2(acc[mt][nt][0] + bz0, acc[mt][nt][1] + bz1);
            float2 v1 = make_float2(acc[mt][nt][2] + bz0, acc[mt][nt][3] + bz1);
            *(float2*)(C + row0 * (size_t)N + col)       = v0;
            *(float2*)(C + (row0 + 8) * (size_t)N + col) = v1;
        }
    }
}

// ------------------------------- rotary ------------------------------------
__global__ __launch_bounds__(256)
void rotary_kernel(const float* __restrict__ qp, const float* __restrict__ kp,
                   float* __restrict__ qo, float* __restrict__ ko)
{
    int idx = blockIdx.x * blockDim.x + threadIdx.x;
    if (idx >= NROWS * 512) return;
    int r = idx >> 9;
    int p = idx & 511;
    int h = p >> 5;
    int i = p & 31;
    int n = r & (SEQ - 1);
    int b = r >> 12;

    float invf  = __powf(10000.f, (-2.f / 64.f) * (float)i);
    float theta = (float)n * invf;
    float s, c;
    sincosf(theta, &s, &c);

    size_t src = (size_t)r * 1024 + h * 64 + i;
    float q0 = qp[src], q1 = qp[src + 32];
    float k0 = kp[src], k1 = kp[src + 32];

    size_t dst = (((size_t)(b * NHEADS + h)) * SEQ + n) * 64 + i;
    const float SC = 0.125f;
    qo[dst]      = (q0 * c - q1 * s) * SC;
    qo[dst + 32] = (q1 * c + q0 * s) * SC;
    ko[dst]      = k0 * c - k1 * s;
    ko[dst + 32] = k1 * c + k0 * s;
}

// ------------------------- global kv aggregation ---------------------------
__global__ __launch_bounds__(32)
void gkv_kernel(const float* __restrict__ kv, const float* __restrict__ Wproj,
                const float* __restrict__ gg, const float* __restrict__ gb,
                float* __restrict__ gkv)
{
    __shared__ float skv[16 * 68];
    __shared__ float swp[64];
    __shared__ float slog[16];

    const int seg  = blockIdx.x;
    const int bh   = blockIdx.y;
    const int lane = threadIdx.x;

    const float* base = kv + ((size_t)bh * SEQ + seg * 16) * 64;
    for (int i = lane; i < 256; i += 32) {
        int s = i >> 4, d4 = (i & 15) << 2;
        *(float4*)&skv[s * 68 + d4] = *(const float4*)(base + s * 64 + d4);
    }
    if (lane < 16) *(float4*)&swp[lane * 4] = *(const float4*)(Wproj + lane * 4);
    __syncwarp();

    if (lane < 16) {
        float a = 0.f;
        #pragma unroll
        for (int d = 0; d < 64; d++) a += skv[lane * 68 + d] * swp[d];
        slog[lane] = a;
    }
    __syncwarp();

    float mx = -1e30f;
    #pragma unroll
    for (int s = 0; s < 16; s++) mx = fmaxf(mx, slog[s]);
    float se = 0.f;
    #pragma unroll
    for (int s = 0; s < 16; s++) se += __expf(slog[s] - mx);
    float inv = 1.f / se;

    float g0 = 0.f, g1 = 0.f;
    #pragma unroll
    for (int s = 0; s < 16; s++) {
        float ps = __expf(slog[s] - mx) * inv;
        g0 += ps * skv[s * 68 + lane];
        g1 += ps * skv[s * 68 + lane + 32];
    }

    float sum = g0 + g1, sq = g0 * g0 + g1 * g1;
    #pragma unroll
    for (int o = 16; o; o >>= 1) {
        sum += __shfl_xor_sync(0xffffffffu, sum, o);
        sq  += __shfl_xor_sync(0xffffffffu, sq, o);
    }
    float mean = sum * (1.f / 64.f);
    float var  = sq * (1.f / 64.f) - mean * mean;
    float rstd = rsqrtf(var + 1e-5f);

    float* outp = gkv + ((size_t)bh * NSEG + seg) * 64;
    outp[lane]      = (g0 - mean) * rstd * gg[lane]      + gb[lane];
    outp[lane + 32] = (g1 - mean) * rstd * gg[lane + 32] + gb[lane + 32];
}

// ------------------------------ attention ----------------------------------
#define KSTRIDE 68
#define FMAX 16.0f

__global__ __launch_bounds__(512, 1)
void attn_kernel(const float* __restrict__ q, const float* __restrict__ kv,
                 const float* __restrict__ gkv, const float* __restrict__ lng_,
                 const float* __restrict__ lnb_, __half* __restrict__ out)
{
    extern __shared__ float keys[];     // [512][KSTRIDE]
    __shared__ float s_lng[64], s_lnb[64];

    const int w   = blockIdx.x;
    const int bh  = blockIdx.y;
    const int tid = threadIdx.x;

    if (tid < 64)  { s_lng[tid] = lng_[tid]; s_lnb[tid] = lnb_[tid]; }

    const float* gbase = gkv + (size_t)bh * NSEG * 64;
    for (int idx = tid; idx < 4096; idx += 512) {
        int j = idx >> 4, d4 = (idx & 15) << 2;
        *(float4*)&keys[j * KSTRIDE + d4] = *(const float4*)(gbase + j * 64 + d4);
    }
    const int pos0 = (w - 1) * WIN;
    const float* kbase = kv + (size_t)bh * SEQ * 64;
    for (int idx = tid; idx < 4096; idx += 512) {
        int jj = idx >> 4, d4 = (idx & 15) << 2;
        int pos = pos0 + jj;
        float4 v = make_float4(0.f, 0.f, 0.f, 0.f);
        if (pos >= 0) v = *(const float4*)(kbase + (size_t)pos * 64 + d4);
        *(float4*)&keys[(256 + jj) * KSTRIDE + d4] = v;
    }
    __syncthreads();

    if (tid < 256) {
        int jj = tid;
        if (pos0 + jj >= 0) {
            float* rowp = &keys[(256 + jj) * KSTRIDE];
            float sum = 0.f, sq = 0.f;
            #pragma unroll
            for (int d = 0; d < 64; d++) { float v = rowp[d]; sum += v; sq += v * v; }
            float mean = sum * (1.f / 64.f);
            float var  = sq * (1.f / 64.f) - mean * mean;
            float rstd = rsqrtf(var + 1e-5f);
            #pragma unroll
            for (int d = 0; d < 64; d++)
                rowp[d] = (rowp[d] - mean) * rstd * s_lng[d] + s_lnb[d];
        }
    }
    __syncthreads();

    const int row  = tid >> 2;
    const int quad = tid & 3;
    const int t    = w * WIN + row;
    const int d0   = quad * 16;

    float qr[16], acc[16];
    const float* qp = q + ((size_t)bh * SEQ + t) * 64 + d0;
    #pragma unroll
    for (int m = 0; m < 4; m++) *(float4*)&qr[m * 4] = *(const float4*)(qp + m * 4);
    #pragma unroll
    for (int d = 0; d < 16; d++) acc[d] = 0.f;

    float l = 0.f;

    const int nglobal = t >> 4;
    const int locmax  = 128 + row;
    const int locmin  = (w == 0) ? 128 : 0;

    const int warpid   = tid >> 5;
    const int rowMaxW  = warpid * 8 + 7;
    const int gLimW    = min(NSEG, (w * WIN + rowMaxW) >> 4);
    const int locMaxW  = 128 + rowMaxW;

    #pragma unroll 2
    for (int j = 0; j < gLimW; j++) {
        const float* kp2 = &keys[j * KSTRIDE + d0];
        float kr[16];
        *(float4*)&kr[0]  = *(const float4*)(kp2);
        *(float4*)&kr[4]  = *(const float4*)(kp2 + 4);
        *(float4*)&kr[8]  = *(const float4*)(kp2 + 8);
        *(float4*)&kr[12] = *(const float4*)(kp2 + 12);
        float dp = 0.f;
        #pragma unroll
        for (int d = 0; d < 16; d++) dp += kr[d] * qr[d];
        dp += __shfl_xor_sync(0xffffffffu, dp, 1);
        dp += __shfl_xor_sync(0xffffffffu, dp, 2);
        if (j < nglobal) {
            float p2 = __expf(dp - FMAX);
            l += p2;
            #pragma unroll
            for (int d = 0; d < 16; d++) acc[d] += p2 * kr[d];
        }
    }
    #pragma unroll 2
    for (int jj = locmin; jj <= locMaxW; jj++) {
        const float* kp2 = &keys[(256 + jj) * KSTRIDE + d0];
        float kr[16];
        *(float4*)&kr[0]  = *(const float4*)(kp2);
        *(float4*)&kr[4]  = *(const float4*)(kp2 + 4);
        *(float4*)&kr[8]  = *(const float4*)(kp2 + 8);
        *(float4*)&kr[12] = *(const float4*)(kp2 + 12);
        float dp = 0.f;
        #pragma unroll
        for (int d = 0; d < 16; d++) dp += kr[d] * qr[d];
        dp += __shfl_xor_sync(0xffffffffu, dp, 1);
        dp += __shfl_xor_sync(0xffffffffu, dp, 2);
        if (jj <= locmax) {
            float p2 = __expf(dp - FMAX);
            l += p2;
            #pragma unroll
            for (int d = 0; d < 16; d++) acc[d] += p2 * kr[d];
        }
    }

    float inv = 1.f / l;
    const int b = bh >> 4, h = bh & 15;
    __half* op = out + ((size_t)b * SEQ + t) * 1024 + h * 64 + d0;
    uint32_t o[8];
    #pragma unroll
    for (int m = 0; m < 8; m++) {
        __half2 hh = __floats2half2_rn(acc[2 * m] * inv, acc[2 * m + 1] * inv);
        o[m] = *(uint32_t*)&hh;
    }
    *(uint4*)(op)     = make_uint4(o[0], o[1], o[2], o[3]);
    *(uint4*)(op + 8) = make_uint4(o[4], o[5], o[6], o[7]);
}

// ------------------------------ launcher -----------------------------------
extern "C" void kernel_launch(void* const* d_in, const int* in_sizes, int n_in,
                              void* d_out, int out_size)
{
    const float* x     = (const float*)d_in[0];
    const float* Wq    = (const float*)d_in[1];
    const float* Wkv   = (const float*)d_in[2];
    const float* Wproj = (const float*)d_in[3];
    const float* Wout  = (const float*)d_in[4];
    const float* bout  = (const float*)d_in[5];
    const float* lng   = (const float*)d_in[6];
    const float* lnb   = (const float*)d_in[7];
    const float* gng   = (const float*)d_in[8];
    const float* gnb   = (const float*)d_in[9];
    float* out = (float*)d_out;

    float *qproj, *kvproj, *qb, *kvb, *gkvb;
    __half *xh, *wqh, *wkvh, *wouth, *aouth;
    cudaGetSymbolAddress((void**)&qproj,  g_qproj);
    cudaGetSymbolAddress((void**)&kvproj, g_kvproj);
    cudaGetSymbolAddress((void**)&qb,     g_q);
    cudaGetSymbolAddress((void**)&kvb,    g_kv);
    cudaGetSymbolAddress((void**)&gkvb,   g_gkv);
    cudaGetSymbolAddress((void**)&xh,     g_xh);
    cudaGetSymbolAddress((void**)&wqh,    g_wqh);
    cudaGetSymbolAddress((void**)&wkvh,   g_wkvh);
    cudaGetSymbolAddress((void**)&wouth,  g_wouth);
    cudaGetSymbolAddress((void**)&aouth,  g_aouth);

    // fp32 -> fp16 operand conversion (bit-identical to in-GEMM rounding)
    const int nx = NROWS * 1024, nw = 1024 * 1024;
    cvt_f2h<<<nx / (256 * 8), 256>>>(x,    xh,    nx);
    cvt_f2h<<<nw / (256 * 8), 256>>>(Wq,   wqh,   nw);
    cvt_f2h<<<nw / (256 * 8), 256>>>(Wkv,  wkvh,  nw);
    cvt_f2h<<<nw / (256 * 8), 256>>>(Wout, wouth, nw);

    dim3 gg1(1024 / 128, NROWS / 128);     // (8, 128)
    gemm_f16ldm<<<gg1, 256>>>(xh, wqh,  nullptr, qproj,  NROWS, 1024, 1024);
    gemm_f16ldm<<<gg1, 256>>>(xh, wkvh, nullptr, kvproj, NROWS, 1024, 1024);

    rotary_kernel<<<(NROWS * 512) / 256, 256>>>(qproj, kvproj, qb, kvb);

    gkv_kernel<<<dim3(NSEG, BHDIM), 32>>>(kvb, Wproj, gng, gnb, gkvb);

    int smem = 512 * KSTRIDE * sizeof(float);   // 139264 B
    cudaFuncSetAttribute(attn_kernel, cudaFuncAttributeMaxDynamicSharedMemorySize, smem);
    attn_kernel<<<dim3(NWIN, BHDIM), 512, smem>>>(qb, kvb, gkvb, lng, lnb, aouth);

    gemm_f16ldm<<<gg1, 256>>>(aouth, wouth, bout, out, NROWS, 1024, 1024);
}

// round 12
// speedup vs baseline: 1.2763x; 1.0127x over previous
#include <cuda_runtime.h>
#include <cuda_fp16.h>
#include <cstdint>

// ---------------------------------------------------------------------------
// LongShortAttention  (B=4, N=4096, DIM=1024, H=16, DH=64, W=128, S=16, R=1)
// R11: two-phase attention (global keys, then local keys reusing the SAME
// 256-row smem buffer) -> smem 139KB -> 69.6KB -> 2 blocks/SM.  Bit-identical
// arithmetic to R10.  GEMM/rotary/gkv unchanged from R10.
// ---------------------------------------------------------------------------

#define NROWS   16384          // B*N
#define SEQ     4096
#define NHEADS  16
#define DH      64
#define BHDIM   64             // B*HEADS
#define WIN     128
#define NWIN    32
#define NSEG    256

// -------------------- scratch (static device globals) ----------------------
__device__ float  g_qproj [(size_t)NROWS * 1024];
__device__ float  g_kvproj[(size_t)NROWS * 1024];
__device__ float  g_q     [(size_t)NROWS * 1024];   // [bh][n][64]
__device__ float  g_kv    [(size_t)NROWS * 1024];   // [bh][n][64]
__device__ float  g_gkv   [(size_t)BHDIM * NSEG * DH];
__device__ __half g_xh    [(size_t)NROWS * 1024];
__device__ __half g_wqh   [1024 * 1024];
__device__ __half g_wkvh  [1024 * 1024];
__device__ __half g_wouth [1024 * 1024];
__device__ __half g_aouth [(size_t)NROWS * 1024];   // [b][t][h*64+d]

// ------------------------------ helpers ------------------------------------
__device__ __forceinline__ void mma_f16(float* c, const uint32_t* a, const uint32_t* b) {
    asm volatile(
        "mma.sync.aligned.m16n8k16.row.col.f32.f16.f16.f32 "
        "{%0,%1,%2,%3}, {%4,%5,%6,%7}, {%8,%9}, {%0,%1,%2,%3};"
        : "+f"(c[0]), "+f"(c[1]), "+f"(c[2]), "+f"(c[3])
        : "r"(a[0]), "r"(a[1]), "r"(a[2]), "r"(a[3]), "r"(b[0]), "r"(b[1]));
}

__device__ __forceinline__ void ldm_x4(uint32_t* r, uint32_t addr) {
    asm volatile("ldmatrix.sync.aligned.m8n8.x4.shared.b16 {%0,%1,%2,%3}, [%4];"
        : "=r"(r[0]), "=r"(r[1]), "=r"(r[2]), "=r"(r[3]) : "r"(addr));
}

__device__ __forceinline__ void ldm_x4_t(uint32_t* r, uint32_t addr) {
    asm volatile("ldmatrix.sync.aligned.m8n8.x4.trans.shared.b16 {%0,%1,%2,%3}, [%4];"
        : "=r"(r[0]), "=r"(r[1]), "=r"(r[2]), "=r"(r[3]) : "r"(addr));
}

// ------------------------ fp32 -> fp16 conversion --------------------------
__global__ __launch_bounds__(256)
void cvt_f2h(const float* __restrict__ src, __half* __restrict__ dst, int n)
{
    int i = (blockIdx.x * blockDim.x + threadIdx.x) * 8;
    if (i >= n) return;
    float4 v0 = *(const float4*)(src + i);
    float4 v1 = *(const float4*)(src + i + 4);
    __half2 h0 = __floats2half2_rn(v0.x, v0.y);
    __half2 h1 = __floats2half2_rn(v0.z, v0.w);
    __half2 h2 = __floats2half2_rn(v1.x, v1.y);
    __half2 h3 = __floats2half2_rn(v1.z, v1.w);
    uint4 u;
    u.x = *(uint32_t*)&h0; u.y = *(uint32_t*)&h1;
    u.z = *(uint32_t*)&h2; u.w = *(uint32_t*)&h3;
    *(uint4*)(dst + i) = u;
}

// --------------------------- f16 tiled GEMM (R10) --------------------------
#define A_STR 80
#define B_STR 272

__global__ __launch_bounds__(256, 2)
void gemm_f16ldm(const __half* __restrict__ A, const __half* __restrict__ B,
                 const float* __restrict__ bias, float* __restrict__ C,
                 int M, int N, int K)
{
    __shared__ __align__(16) char sA[128 * A_STR];   // 10240 B
    __shared__ __align__(16) char sB[32 * B_STR];    // 8704 B

    const int tid = threadIdx.x;
    const size_t bM = (size_t)blockIdx.y * 128;
    const size_t bN = (size_t)blockIdx.x * 128;

    const __half* Ab = A + bM * (size_t)K;
    const __half* Bb = B + bN;

    const int aRow = tid >> 2;
    const int aOff = tid & 3;
    const int bRow = tid >> 4;
    const int bOff = tid & 15;

    const int wid  = tid >> 5;
    const int lane = tid & 31;
    const int wm   = wid >> 2;
    const int wn   = wid & 3;
    const int mbase = wm * 64;
    const int nbase = wn * 32;
    const int g  = lane >> 2;
    const int tg = lane & 3;
    const int part = lane >> 3;
    const int r8   = lane & 7;

    const uint32_t sA32 = (uint32_t)__cvta_generic_to_shared(sA);
    const uint32_t sB32 = (uint32_t)__cvta_generic_to_shared(sB);

    float acc[4][4][4];
    #pragma unroll
    for (int mt = 0; mt < 4; mt++)
        #pragma unroll
        for (int nt = 0; nt < 4; nt++)
            #pragma unroll
            for (int r = 0; r < 4; r++) acc[mt][nt][r] = 0.f;

    uint4 pa0 = *(const uint4*)(Ab + (size_t)aRow        * K + aOff * 8);
    uint4 pa1 = *(const uint4*)(Ab + (size_t)(aRow + 64) * K + aOff * 8);
    uint4 pb0 = *(const uint4*)(Bb + (size_t)bRow        * N + bOff * 8);
    uint4 pb1 = *(const uint4*)(Bb + (size_t)(bRow + 16) * N + bOff * 8);

    const int nKT = K / 32;
    for (int kt = 0; kt < nKT; kt++) {
        *(uint4*)(sA + aRow        * A_STR + aOff * 16) = pa0;
        *(uint4*)(sA + (aRow + 64) * A_STR + aOff * 16) = pa1;
        *(uint4*)(sB + bRow        * B_STR + bOff * 16) = pb0;
        *(uint4*)(sB + (bRow + 16) * B_STR + bOff * 16) = pb1;
        __syncthreads();

        if (kt + 1 < nKT) {
            const int k0 = (kt + 1) * 32;
            pa0 = *(const uint4*)(Ab + (size_t)aRow        * K + k0 + aOff * 8);
            pa1 = *(const uint4*)(Ab + (size_t)(aRow + 64) * K + k0 + aOff * 8);
            pb0 = *(const uint4*)(Bb + (size_t)(k0 + bRow)      * N + bOff * 8);
            pb1 = *(const uint4*)(Bb + (size_t)(k0 + bRow + 16) * N + bOff * 8);
        }

        #pragma unroll
        for (int ks = 0; ks < 2; ks++) {
            uint32_t afr[4][4], bfr[4][2];
            #pragma unroll
            for (int mt = 0; mt < 4; mt++) {
                const int row = mbase + mt * 16 + r8 + (part & 1) * 8;
                const uint32_t byte = (uint32_t)(ks * 32 + (part >> 1) * 16);
                ldm_x4(afr[mt], sA32 + row * A_STR + byte);
            }
            #pragma unroll
            for (int np = 0; np < 2; np++) {
                uint32_t t[4];
                const int row = ks * 16 + r8 + (part & 1) * 8;
                const uint32_t byte = (uint32_t)((nbase + np * 16) * 2 + (part >> 1) * 16);
                ldm_x4_t(t, sB32 + row * B_STR + byte);
                bfr[2 * np][0]     = t[0];
                bfr[2 * np][1]     = t[1];
                bfr[2 * np + 1][0] = t[2];
                bfr[2 * np + 1][1] = t[3];
            }
            #pragma unroll
            for (int mt = 0; mt < 4; mt++)
                #pragma unroll
                for (int nt = 0; nt < 4; nt++)
                    mma_f16(acc[mt][nt], afr[mt], bfr[nt]);
        }
        __syncthreads();
    }

    #pragma unroll
    for (int mt = 0; mt < 4; mt++) {
        const size_t row0 = bM + mbase + mt * 16 + g;
        #pragma unroll
        for (int nt = 0; nt < 4; nt++) {
            const size_t col = bN + nbase + nt * 8 + tg * 2;
            float bz0 = 0.f, bz1 = 0.f;
            if (bias) { bz0 = bias[col]; bz1 = bias[col + 1]; }
            float2 v0 = make_float2(acc[mt][nt][0] + bz0, acc[mt][nt][1] + bz1);
            float2 v1 = make_float2(acc[mt][nt][2] + bz0, acc[mt][nt][3] + bz1);
            *(float2*)(C + row0 * (size_t)N + col)       = v0;
            *(float2*)(C + (row0 + 8) * (size_t)N + col) = v1;
        }
    }
}

// ------------------------------- rotary ------------------------------------
__global__ __launch_bounds__(256)
void rotary_kernel(const float* __restrict__ qp, const float* __restrict__ kp,
                   float* __restrict__ qo, float* __restrict__ ko)
{
    int idx = blockIdx.x * blockDim.x + threadIdx.x;
    if (idx >= NROWS * 512) return;
    int r = idx >> 9;
    int p = idx & 511;
    int h = p >> 5;
    int i = p & 31;
    int n = r & (SEQ - 1);
    int b = r >> 12;

    float invf  = __powf(10000.f, (-2.f / 64.f) * (float)i);
    float theta = (float)n * invf;
    float s, c;
    sincosf(theta, &s, &c);

    size_t src = (size_t)r * 1024 + h * 64 + i;
    float q0 = qp[src], q1 = qp[src + 32];
    float k0 = kp[src], k1 = kp[src + 32];

    size_t dst = (((size_t)(b * NHEADS + h)) * SEQ + n) * 64 + i;
    const float SC = 0.125f;
    qo[dst]      = (q0 * c - q1 * s) * SC;
    qo[dst + 32] = (q1 * c + q0 * s) * SC;
    ko[dst]      = k0 * c - k1 * s;
    ko[dst + 32] = k1 * c + k0 * s;
}

// ------------------------- global kv aggregation ---------------------------
__global__ __launch_bounds__(32)
void gkv_kernel(const float* __restrict__ kv, const float* __restrict__ Wproj,
                const float* __restrict__ gg, const float* __restrict__ gb,
                float* __restrict__ gkv)
{
    __shared__ float skv[16 * 68];
    __shared__ float swp[64];
    __shared__ float slog[16];

    const int seg  = blockIdx.x;
    const int bh   = blockIdx.y;
    const int lane = threadIdx.x;

    const float* base = kv + ((size_t)bh * SEQ + seg * 16) * 64;
    for (int i = lane; i < 256; i += 32) {
        int s = i >> 4, d4 = (i & 15) << 2;
        *(float4*)&skv[s * 68 + d4] = *(const float4*)(base + s * 64 + d4);
    }
    if (lane < 16) *(float4*)&swp[lane * 4] = *(const float4*)(Wproj + lane * 4);
    __syncwarp();

    if (lane < 16) {
        float a = 0.f;
        #pragma unroll
        for (int d = 0; d < 64; d++) a += skv[lane * 68 + d] * swp[d];
        slog[lane] = a;
    }
    __syncwarp();

    float mx = -1e30f;
    #pragma unroll
    for (int s = 0; s < 16; s++) mx = fmaxf(mx, slog[s]);
    float se = 0.f;
    #pragma unroll
    for (int s = 0; s < 16; s++) se += __expf(slog[s] - mx);
    float inv = 1.f / se;

    float g0 = 0.f, g1 = 0.f;
    #pragma unroll
    for (int s = 0; s < 16; s++) {
        float ps = __expf(slog[s] - mx) * inv;
        g0 += ps * skv[s * 68 + lane];
        g1 += ps * skv[s * 68 + lane + 32];
    }

    float sum = g0 + g1, sq = g0 * g0 + g1 * g1;
    #pragma unroll
    for (int o = 16; o; o >>= 1) {
        sum += __shfl_xor_sync(0xffffffffu, sum, o);
        sq  += __shfl_xor_sync(0xffffffffu, sq, o);
    }
    float mean = sum * (1.f / 64.f);
    float var  = sq * (1.f / 64.f) - mean * mean;
    float rstd = rsqrtf(var + 1e-5f);

    float* outp = gkv + ((size_t)bh * NSEG + seg) * 64;
    outp[lane]      = (g0 - mean) * rstd * gg[lane]      + gb[lane];
    outp[lane + 32] = (g1 - mean) * rstd * gg[lane + 32] + gb[lane + 32];
}

// ------------------------------ attention ----------------------------------
// Two-phase: phase A = 256 global keys; phase B = 256 local keys (same smem).
// smem 256*68*4 = 69632 B -> 2 blocks/SM.  Arithmetic identical to R10.
#define KSTRIDE 68
#define FMAX 16.0f

__global__ __launch_bounds__(512, 2)
void attn_kernel(const float* __restrict__ q, const float* __restrict__ kv,
                 const float* __restrict__ gkv, const float* __restrict__ lng_,
                 const float* __restrict__ lnb_, __half* __restrict__ out)
{
    extern __shared__ float keys[];     // [256][KSTRIDE]
    __shared__ float s_lng[64], s_lnb[64];

    const int w   = blockIdx.x;
    const int bh  = blockIdx.y;
    const int tid = threadIdx.x;

    if (tid < 64)  { s_lng[tid] = lng_[tid]; s_lnb[tid] = lnb_[tid]; }

    const int row  = tid >> 2;
    const int quad = tid & 3;
    const int t    = w * WIN + row;
    const int d0   = quad * 16;

    const int warpid  = tid >> 5;
    const int rowMaxW = warpid * 8 + 7;

    float qr[16], acc[16];
    const float* qp = q + ((size_t)bh * SEQ + t) * 64 + d0;
    #pragma unroll
    for (int m = 0; m < 4; m++) *(float4*)&qr[m * 4] = *(const float4*)(qp + m * 4);
    #pragma unroll
    for (int d = 0; d < 16; d++) acc[d] = 0.f;
    float l = 0.f;

    // ======================= phase A: global keys =========================
    {
        const float* gbase = gkv + (size_t)bh * NSEG * 64;
        for (int idx = tid; idx < 4096; idx += 512) {
            int j = idx >> 4, d4 = (idx & 15) << 2;
            *(float4*)&keys[j * KSTRIDE + d4] = *(const float4*)(gbase + j * 64 + d4);
        }
        __syncthreads();

        const int nglobal = t >> 4;
        const int gLimW   = min(NSEG, (w * WIN + rowMaxW) >> 4);

        #pragma unroll 2
        for (int j = 0; j < gLimW; j++) {
            const float* kp2 = &keys[j * KSTRIDE + d0];
            float kr[16];
            *(float4*)&kr[0]  = *(const float4*)(kp2);
            *(float4*)&kr[4]  = *(const float4*)(kp2 + 4);
            *(float4*)&kr[8]  = *(const float4*)(kp2 + 8);
            *(float4*)&kr[12] = *(const float4*)(kp2 + 12);
            float dp = 0.f;
            #pragma unroll
            for (int d = 0; d < 16; d++) dp += kr[d] * qr[d];
            dp += __shfl_xor_sync(0xffffffffu, dp, 1);
            dp += __shfl_xor_sync(0xffffffffu, dp, 2);
            if (j < nglobal) {
                float p2 = __expf(dp - FMAX);
                l += p2;
                #pragma unroll
                for (int d = 0; d < 16; d++) acc[d] += p2 * kr[d];
            }
        }
        __syncthreads();   // everyone done reading global keys
    }

    // ======================= phase B: local keys ==========================
    {
        const int pos0 = (w - 1) * WIN;
        const float* kbase = kv + (size_t)bh * SEQ * 64;
        for (int idx = tid; idx < 4096; idx += 512) {
            int jj = idx >> 4, d4 = (idx & 15) << 2;
            int pos = pos0 + jj;
            float4 v = make_float4(0.f, 0.f, 0.f, 0.f);
            if (pos >= 0) v = *(const float4*)(kbase + (size_t)pos * 64 + d4);
            *(float4*)&keys[jj * KSTRIDE + d4] = v;
        }
        __syncthreads();

        // layernorm local rows in place
        if (tid < 256) {
            int jj = tid;
            if (pos0 + jj >= 0) {
                float* rowp = &keys[jj * KSTRIDE];
                float sum = 0.f, sq = 0.f;
                #pragma unroll
                for (int d = 0; d < 64; d++) { float v = rowp[d]; sum += v; sq += v * v; }
                float mean = sum * (1.f / 64.f);
                float var  = sq * (1.f / 64.f) - mean * mean;
                float rstd = rsqrtf(var + 1e-5f);
                #pragma unroll
                for (int d = 0; d < 64; d++)
                    rowp[d] = (rowp[d] - mean) * rstd * s_lng[d] + s_lnb[d];
            }
        }
        __syncthreads();

        const int locmax  = 128 + row;
        const int locmin  = (w == 0) ? 128 : 0;
        const int locMaxW = 128 + rowMaxW;

        #pragma unroll 2
        for (int jj = locmin; jj <= locMaxW; jj++) {
            const float* kp2 = &keys[jj * KSTRIDE + d0];
            float kr[16];
            *(float4*)&kr[0]  = *(const float4*)(kp2);
            *(float4*)&kr[4]  = *(const float4*)(kp2 + 4);
            *(float4*)&kr[8]  = *(const float4*)(kp2 + 8);
            *(float4*)&kr[12] = *(const float4*)(kp2 + 12);
            float dp = 0.f;
            #pragma unroll
            for (int d = 0; d < 16; d++) dp += kr[d] * qr[d];
            dp += __shfl_xor_sync(0xffffffffu, dp, 1);
            dp += __shfl_xor_sync(0xffffffffu, dp, 2);
            if (jj <= locmax) {
                float p2 = __expf(dp - FMAX);
                l += p2;
                #pragma unroll
                for (int d = 0; d < 16; d++) acc[d] += p2 * kr[d];
            }
        }
    }

    float inv = 1.f / l;
    const int b = bh >> 4, h = bh & 15;
    __half* op = out + ((size_t)b * SEQ + t) * 1024 + h * 64 + d0;
    uint32_t o[8];
    #pragma unroll
    for (int m = 0; m < 8; m++) {
        __half2 hh = __floats2half2_rn(acc[2 * m] * inv, acc[2 * m + 1] * inv);
        o[m] = *(uint32_t*)&hh;
    }
    *(uint4*)(op)     = make_uint4(o[0], o[1], o[2], o[3]);
    *(uint4*)(op + 8) = make_uint4(o[4], o[5], o[6], o[7]);
}

// ------------------------------ launcher -----------------------------------
extern "C" void kernel_launch(void* const* d_in, const int* in_sizes, int n_in,
                              void* d_out, int out_size)
{
    const float* x     = (const float*)d_in[0];
    const float* Wq    = (const float*)d_in[1];
    const float* Wkv   = (const float*)d_in[2];
    const float* Wproj = (const float*)d_in[3];
    const float* Wout  = (const float*)d_in[4];
    const float* bout  = (const float*)d_in[5];
    const float* lng   = (const float*)d_in[6];
    const float* lnb   = (const float*)d_in[7];
    const float* gng   = (const float*)d_in[8];
    const float* gnb   = (const float*)d_in[9];
    float* out = (float*)d_out;

    float *qproj, *kvproj, *qb, *kvb, *gkvb;
    __half *xh, *wqh, *wkvh, *wouth, *aouth;
    cudaGetSymbolAddress((void**)&qproj,  g_qproj);
    cudaGetSymbolAddress((void**)&kvproj, g_kvproj);
    cudaGetSymbolAddress((void**)&qb,     g_q);
    cudaGetSymbolAddress((void**)&kvb,    g_kv);
    cudaGetSymbolAddress((void**)&gkvb,   g_gkv);
    cudaGetSymbolAddress((void**)&xh,     g_xh);
    cudaGetSymbolAddress((void**)&wqh,    g_wqh);
    cudaGetSymbolAddress((void**)&wkvh,   g_wkvh);
    cudaGetSymbolAddress((void**)&wouth,  g_wouth);
    cudaGetSymbolAddress((void**)&aouth,  g_aouth);

    const int nx = NROWS * 1024, nw = 1024 * 1024;
    cvt_f2h<<<nx / (256 * 8), 256>>>(x,    xh,    nx);
    cvt_f2h<<<nw / (256 * 8), 256>>>(Wq,   wqh,   nw);
    cvt_f2h<<<nw / (256 * 8), 256>>>(Wkv,  wkvh,  nw);
    cvt_f2h<<<nw / (256 * 8), 256>>>(Wout, wouth, nw);

    dim3 gg1(1024 / 128, NROWS / 128);     // (8, 128)
    gemm_f16ldm<<<gg1, 256>>>(xh, wqh,  nullptr, qproj,  NROWS, 1024, 1024);
    gemm_f16ldm<<<gg1, 256>>>(xh, wkvh, nullptr, kvproj, NROWS, 1024, 1024);

    rotary_kernel<<<(NROWS * 512) / 256, 256>>>(qproj, kvproj, qb, kvb);

    gkv_kernel<<<dim3(NSEG, BHDIM), 32>>>(kvb, Wproj, gng, gnb, gkvb);

    int smem = 256 * KSTRIDE * sizeof(float);   // 69632 B
    cudaFuncSetAttribute(attn_kernel, cudaFuncAttributeMaxDynamicSharedMemorySize, smem);
    attn_kernel<<<dim3(NWIN, BHDIM), 512, smem>>>(qb, kvb, gkvb, lng, lnb, aouth);

    gemm_f16ldm<<<gg1, 256>>>(aouth, wouth, bout, out, NROWS, 1024, 1024);
}